// round 1
// baseline (speedup 1.0000x reference)
#include <cuda_runtime.h>

#define NUSERS 100000
#define NITEMS 200000
#define DIM    128
#define NEDGES 2000000
#define LN_EPS 1e-5f

// ---------------- scratch (device globals; no allocations allowed) ----------
__device__ __align__(16) float g_u_temp[NUSERS * DIM];
__device__ __align__(16) float g_i_temp[NITEMS * DIM];
__device__ __align__(16) float g_u_buf [NUSERS * DIM];
__device__ __align__(16) float g_i_buf [NITEMS * DIM];

// ---------------- helpers ----------------------------------------------------
__device__ __forceinline__ void red_add_v4(float* a, float x, float y, float z, float w) {
    asm volatile("red.global.add.v4.f32 [%0], {%1, %2, %3, %4};"
                 :: "l"(a), "f"(x), "f"(y), "f"(z), "f"(w) : "memory");
}

// ---------------- zero the accumulators --------------------------------------
__global__ void zero_temps_kernel() {
    int idx = blockIdx.x * blockDim.x + threadIdx.x;
    const int nu4 = NUSERS * DIM / 4;   // 3.2M
    const int ni4 = NITEMS * DIM / 4;   // 6.4M
    float4 z = make_float4(0.f, 0.f, 0.f, 0.f);
    if (idx < nu4) reinterpret_cast<float4*>(g_u_temp)[idx] = z;
    if (idx < ni4) reinterpret_cast<float4*>(g_i_temp)[idx] = z;
}

// ---------------- edge scatter: both directions in one pass ------------------
// warp per edge; lane l handles floats [4l, 4l+4)
__global__ void __launch_bounds__(256) edge_scatter_kernel(
        const float* __restrict__ u_emb,
        const float* __restrict__ i_emb,
        const float* __restrict__ vals,
        const int*   __restrict__ rows,
        const int*   __restrict__ cols) {
    int gw   = (blockIdx.x * blockDim.x + threadIdx.x) >> 5;
    int lane = threadIdx.x & 31;
    if (gw >= NEDGES) return;

    int r = 0, c = 0; float v = 0.f;
    if (lane == 0) {
        r = rows[gw];
        c = cols[gw];
        v = vals[gw];
    }
    r = __shfl_sync(0xffffffffu, r, 0);
    c = __shfl_sync(0xffffffffu, c, 0);
    v = __shfl_sync(0xffffffffu, v, 0);

    const float4* u4 = reinterpret_cast<const float4*>(u_emb);
    const float4* i4 = reinterpret_cast<const float4*>(i_emb);

    float4 iv = __ldg(&i4[c * 32 + lane]);   // row of item table
    float4 uv = __ldg(&u4[r * 32 + lane]);   // row of user table

    // u_temp[r] += v * i_emb[c]
    red_add_v4(&g_u_temp[r * DIM + lane * 4], v * iv.x, v * iv.y, v * iv.z, v * iv.w);
    // i_temp[c] += v * u_emb[r]
    red_add_v4(&g_i_temp[c * DIM + lane * 4], v * uv.x, v * uv.y, v * uv.z, v * uv.w);
}

// ---------------- residual + LayerNorm (warp per row), optional temp re-zero -
template <bool ZERO_TEMPS>
__global__ void __launch_bounds__(256) ln_kernel(
        const float* __restrict__ u_in,
        const float* __restrict__ i_in,
        const float* __restrict__ gamma,
        const float* __restrict__ beta,
        float* __restrict__ u_out,
        float* __restrict__ i_out) {
    int w    = (blockIdx.x * blockDim.x + threadIdx.x) >> 5;
    int lane = threadIdx.x & 31;
    if (w >= NUSERS + NITEMS) return;

    const float4* in4;
    float4*       t4;
    float4*       out4;
    int row;
    if (w < NUSERS) {
        in4  = reinterpret_cast<const float4*>(u_in);
        t4   = reinterpret_cast<float4*>(g_u_temp);
        out4 = reinterpret_cast<float4*>(u_out);
        row  = w;
    } else {
        in4  = reinterpret_cast<const float4*>(i_in);
        t4   = reinterpret_cast<float4*>(g_i_temp);
        out4 = reinterpret_cast<float4*>(i_out);
        row  = w - NUSERS;
    }

    int off = row * 32 + lane;
    float4 a = __ldg(&in4[off]);
    float4 t = t4[off];
    if (ZERO_TEMPS) t4[off] = make_float4(0.f, 0.f, 0.f, 0.f);

    float4 x;
    x.x = a.x + t.x; x.y = a.y + t.y; x.z = a.z + t.z; x.w = a.w + t.w;

    float s  = x.x + x.y + x.z + x.w;
    float sq = x.x * x.x + x.y * x.y + x.z * x.z + x.w * x.w;
#pragma unroll
    for (int o = 16; o > 0; o >>= 1) {
        s  += __shfl_xor_sync(0xffffffffu, s,  o);
        sq += __shfl_xor_sync(0xffffffffu, sq, o);
    }
    float m    = s * (1.f / DIM);
    float var  = sq * (1.f / DIM) - m * m;
    float rstd = rsqrtf(var + LN_EPS);

    float4 g = __ldg(&reinterpret_cast<const float4*>(gamma)[lane]);
    float4 b = __ldg(&reinterpret_cast<const float4*>(beta )[lane]);

    float4 o;
    o.x = g.x * (x.x - m) * rstd + b.x;
    o.y = g.y * (x.y - m) * rstd + b.y;
    o.z = g.z * (x.z - m) * rstd + b.z;
    o.w = g.w * (x.w - m) * rstd + b.w;
    out4[off] = o;
}

// ---------------- launch -----------------------------------------------------
extern "C" void kernel_launch(void* const* d_in, const int* in_sizes, int n_in,
                              void* d_out, int out_size) {
    const float* user_emb = (const float*)d_in[0];
    const float* item_emb = (const float*)d_in[1];
    const float* vals     = (const float*)d_in[2];
    const float* gamma    = (const float*)d_in[3];
    const float* beta     = (const float*)d_in[4];
    const int*   rows     = (const int*)d_in[5];
    const int*   cols     = (const int*)d_in[6];

    float* out   = (float*)d_out;
    float* u_out = out;
    float* i_out = out + (size_t)NUSERS * DIM;

    void* p_u_buf = nullptr; void* p_i_buf = nullptr;
    cudaGetSymbolAddress(&p_u_buf, g_u_buf);
    cudaGetSymbolAddress(&p_i_buf, g_i_buf);
    float* u_buf = (float*)p_u_buf;
    float* i_buf = (float*)p_i_buf;

    const int zero_blocks    = (NITEMS * DIM / 4 + 255) / 256;        // 25000
    const int scatter_blocks = (NEDGES * 32 + 255) / 256;             // 250000
    const int ln_blocks      = ((NUSERS + NITEMS) * 32 + 255) / 256;  // 37500

    // Layer 1
    zero_temps_kernel<<<zero_blocks, 256>>>();
    edge_scatter_kernel<<<scatter_blocks, 256>>>(user_emb, item_emb, vals, rows, cols);
    ln_kernel<true><<<ln_blocks, 256>>>(user_emb, item_emb, gamma, beta, u_buf, i_buf);

    // Layer 2
    edge_scatter_kernel<<<scatter_blocks, 256>>>(u_buf, i_buf, vals, rows, cols);
    ln_kernel<false><<<ln_blocks, 256>>>(u_buf, i_buf, gamma, beta, u_out, i_out);
}

// round 2
// speedup vs baseline: 1.3976x; 1.3976x over previous
#include <cuda_runtime.h>

#define NUSERS 100000
#define NITEMS 200000
#define DIM    128
#define NEDGES 2000000
#define LN_EPS 1e-5f

#define NBUCKETS (NUSERS + NITEMS)          // combined r-buckets then c-buckets
#define SCAN_BLK 1024
#define NSCANBLK ((NBUCKETS + SCAN_BLK - 1) / SCAN_BLK)   // 293

// ---------------- scratch (device globals; no allocations allowed) ----------
__device__ __align__(16) float g_u_temp[NUSERS * DIM];   // 51.2 MB
__device__ __align__(16) float g_i_temp[NITEMS * DIM];   // 102.4 MB
__device__ __align__(16) float g_u_buf [NUSERS * DIM];   // 51.2 MB
__device__ __align__(16) float g_i_buf [NITEMS * DIM];   // 102.4 MB

// edge lists sorted by bucket key: payload = (other index, value-bits)
__device__ __align__(16) int2 g_by_r[NEDGES];            // key r, payload (c, v)
__device__ __align__(16) int2 g_by_c[NEDGES];            // key c, payload (r, v)

__device__ int g_cnt[NBUCKETS];        // histogram
__device__ int g_off[NBUCKETS + 1];    // pristine exclusive-scan offsets (CSR)
__device__ int g_cur[NBUCKETS];        // working cursors for the build scatter
__device__ int g_bsum[NSCANBLK];       // per-block sums for the scan spine

// ---------------- helpers ----------------------------------------------------
__device__ __forceinline__ void red_add_v4(float* a, float x, float y, float z, float w) {
    asm volatile("red.global.add.v4.f32 [%0], {%1, %2, %3, %4};"
                 :: "l"(a), "f"(x), "f"(y), "f"(z), "f"(w) : "memory");
}

// ---------------- zero temps + counters --------------------------------------
__global__ void zero_all_kernel() {
    int idx = blockIdx.x * blockDim.x + threadIdx.x;
    const int nu4 = NUSERS * DIM / 4;   // 3.2M
    const int ni4 = NITEMS * DIM / 4;   // 6.4M
    float4 z = make_float4(0.f, 0.f, 0.f, 0.f);
    if (idx < nu4) reinterpret_cast<float4*>(g_u_temp)[idx] = z;
    if (idx < ni4) reinterpret_cast<float4*>(g_i_temp)[idx] = z;
    if (idx < NBUCKETS) g_cnt[idx] = 0;
}

// ---------------- histogram ---------------------------------------------------
__global__ void hist_kernel(const int* __restrict__ rows, const int* __restrict__ cols) {
    int e = blockIdx.x * blockDim.x + threadIdx.x;
    if (e >= NEDGES) return;
    atomicAdd(&g_cnt[rows[e]], 1);
    atomicAdd(&g_cnt[NUSERS + cols[e]], 1);
}

// ---------------- scan: per-block sums ----------------------------------------
__global__ void scan_bsum_kernel() {
    __shared__ int s[SCAN_BLK];
    int idx = blockIdx.x * SCAN_BLK + threadIdx.x;
    int v = (idx < NBUCKETS) ? g_cnt[idx] : 0;
    s[threadIdx.x] = v;
    __syncthreads();
    for (int o = SCAN_BLK / 2; o > 0; o >>= 1) {
        if (threadIdx.x < o) s[threadIdx.x] += s[threadIdx.x + o];
        __syncthreads();
    }
    if (threadIdx.x == 0) g_bsum[blockIdx.x] = s[0];
}

// ---------------- scan: spine (serial, tiny) ----------------------------------
__global__ void scan_spine_kernel() {
    if (threadIdx.x == 0 && blockIdx.x == 0) {
        int acc = 0;
        for (int i = 0; i < NSCANBLK; i++) {
            int t = g_bsum[i];
            g_bsum[i] = acc;
            acc += t;
        }
        g_off[NBUCKETS] = acc;   // = 2*NEDGES
    }
}

// ---------------- scan: apply block-local exclusive scan ----------------------
__global__ void scan_apply_kernel() {
    __shared__ int s[SCAN_BLK];
    int idx = blockIdx.x * SCAN_BLK + threadIdx.x;
    int v = (idx < NBUCKETS) ? g_cnt[idx] : 0;
    s[threadIdx.x] = v;
    __syncthreads();
    // Hillis-Steele inclusive scan
    for (int o = 1; o < SCAN_BLK; o <<= 1) {
        int t = (threadIdx.x >= o) ? s[threadIdx.x - o] : 0;
        __syncthreads();
        s[threadIdx.x] += t;
        __syncthreads();
    }
    int excl = s[threadIdx.x] - v + g_bsum[blockIdx.x];
    if (idx < NBUCKETS) {
        g_off[idx] = excl;
        g_cur[idx] = excl;
    }
}

// ---------------- build sorted edge lists -------------------------------------
__global__ void build_kernel(const int* __restrict__ rows,
                             const int* __restrict__ cols,
                             const float* __restrict__ vals) {
    int e = blockIdx.x * blockDim.x + threadIdx.x;
    if (e >= NEDGES) return;
    int r = rows[e];
    int c = cols[e];
    int vb = __float_as_int(vals[e]);
    int p1 = atomicAdd(&g_cur[r], 1);                       // in [0, NEDGES)
    g_by_r[p1] = make_int2(c, vb);
    int p2 = atomicAdd(&g_cur[NUSERS + c], 1) - NEDGES;     // in [0, NEDGES)
    g_by_c[p2] = make_int2(r, vb);
}

// ---------------- u-direction: u_temp[r] += v * i_emb[c], bucketed by c -------
// warp per item bucket c: stream i_emb row once, loop edges, red into u_temp
__global__ void __launch_bounds__(256) u_dir_kernel(const float* __restrict__ i_emb) {
    int c    = (blockIdx.x * blockDim.x + threadIdx.x) >> 5;
    int lane = threadIdx.x & 31;
    if (c >= NITEMS) return;
    int beg = g_off[NUSERS + c] - NEDGES;
    int end = g_off[NUSERS + c + 1] - NEDGES;
    if (beg == end) return;

    float4 emb = __ldg(&reinterpret_cast<const float4*>(i_emb)[c * 32 + lane]);

    for (int p = beg; p < end; p++) {
        int2 pr = __ldg(&g_by_c[p]);     // all lanes same addr -> broadcast
        int   r = pr.x;
        float v = __int_as_float(pr.y);
        red_add_v4(&g_u_temp[r * DIM + lane * 4],
                   v * emb.x, v * emb.y, v * emb.z, v * emb.w);
    }
}

// ---------------- i-direction: i_temp[c] += v * u_emb[r], bucketed by r -------
__global__ void __launch_bounds__(256) i_dir_kernel(const float* __restrict__ u_emb) {
    int r    = (blockIdx.x * blockDim.x + threadIdx.x) >> 5;
    int lane = threadIdx.x & 31;
    if (r >= NUSERS) return;
    int beg = g_off[r];
    int end = g_off[r + 1];
    if (beg == end) return;

    float4 emb = __ldg(&reinterpret_cast<const float4*>(u_emb)[r * 32 + lane]);

    for (int p = beg; p < end; p++) {
        int2 pr = __ldg(&g_by_r[p]);
        int   c = pr.x;
        float v = __int_as_float(pr.y);
        red_add_v4(&g_i_temp[c * DIM + lane * 4],
                   v * emb.x, v * emb.y, v * emb.z, v * emb.w);
    }
}

// ---------------- residual + LayerNorm (warp per row), optional temp re-zero -
template <bool ZERO_TEMPS>
__global__ void __launch_bounds__(256) ln_kernel(
        const float* __restrict__ u_in,
        const float* __restrict__ i_in,
        const float* __restrict__ gamma,
        const float* __restrict__ beta,
        float* __restrict__ u_out,
        float* __restrict__ i_out) {
    int w    = (blockIdx.x * blockDim.x + threadIdx.x) >> 5;
    int lane = threadIdx.x & 31;
    if (w >= NUSERS + NITEMS) return;

    const float4* in4;
    float4*       t4;
    float4*       out4;
    int row;
    if (w < NUSERS) {
        in4  = reinterpret_cast<const float4*>(u_in);
        t4   = reinterpret_cast<float4*>(g_u_temp);
        out4 = reinterpret_cast<float4*>(u_out);
        row  = w;
    } else {
        in4  = reinterpret_cast<const float4*>(i_in);
        t4   = reinterpret_cast<float4*>(g_i_temp);
        out4 = reinterpret_cast<float4*>(i_out);
        row  = w - NUSERS;
    }

    int off = row * 32 + lane;
    float4 a = __ldg(&in4[off]);
    float4 t = t4[off];
    if (ZERO_TEMPS) t4[off] = make_float4(0.f, 0.f, 0.f, 0.f);

    float4 x;
    x.x = a.x + t.x; x.y = a.y + t.y; x.z = a.z + t.z; x.w = a.w + t.w;

    float s  = x.x + x.y + x.z + x.w;
    float sq = x.x * x.x + x.y * x.y + x.z * x.z + x.w * x.w;
#pragma unroll
    for (int o = 16; o > 0; o >>= 1) {
        s  += __shfl_xor_sync(0xffffffffu, s,  o);
        sq += __shfl_xor_sync(0xffffffffu, sq, o);
    }
    float m    = s * (1.f / DIM);
    float var  = sq * (1.f / DIM) - m * m;
    float rstd = rsqrtf(var + LN_EPS);

    float4 g = __ldg(&reinterpret_cast<const float4*>(gamma)[lane]);
    float4 b = __ldg(&reinterpret_cast<const float4*>(beta )[lane]);

    float4 o;
    o.x = g.x * (x.x - m) * rstd + b.x;
    o.y = g.y * (x.y - m) * rstd + b.y;
    o.z = g.z * (x.z - m) * rstd + b.z;
    o.w = g.w * (x.w - m) * rstd + b.w;
    out4[off] = o;
}

// ---------------- launch -----------------------------------------------------
extern "C" void kernel_launch(void* const* d_in, const int* in_sizes, int n_in,
                              void* d_out, int out_size) {
    const float* user_emb = (const float*)d_in[0];
    const float* item_emb = (const float*)d_in[1];
    const float* vals     = (const float*)d_in[2];
    const float* gamma    = (const float*)d_in[3];
    const float* beta     = (const float*)d_in[4];
    const int*   rows     = (const int*)d_in[5];
    const int*   cols     = (const int*)d_in[6];

    float* out   = (float*)d_out;
    float* u_out = out;
    float* i_out = out + (size_t)NUSERS * DIM;

    void* p_u_buf = nullptr; void* p_i_buf = nullptr;
    cudaGetSymbolAddress(&p_u_buf, g_u_buf);
    cudaGetSymbolAddress(&p_i_buf, g_i_buf);
    float* u_buf = (float*)p_u_buf;
    float* i_buf = (float*)p_i_buf;

    const int zero_blocks  = (NITEMS * DIM / 4 + 255) / 256;         // 25000
    const int edge_blocks  = (NEDGES + 255) / 256;                   // 7813
    const int udir_blocks  = (NITEMS * 32 + 255) / 256;              // 25000
    const int idir_blocks  = (NUSERS * 32 + 255) / 256;              // 12500
    const int ln_blocks    = ((NUSERS + NITEMS) * 32 + 255) / 256;   // 37500

    // ---- preprocessing: counting sort of edges by both keys (in-graph) ----
    zero_all_kernel<<<zero_blocks, 256>>>();
    hist_kernel<<<edge_blocks, 256>>>(rows, cols);
    scan_bsum_kernel<<<NSCANBLK, SCAN_BLK>>>();
    scan_spine_kernel<<<1, 32>>>();
    scan_apply_kernel<<<NSCANBLK, SCAN_BLK>>>();
    build_kernel<<<edge_blocks, 256>>>(rows, cols, vals);

    // ---- layer 1 ----
    u_dir_kernel<<<udir_blocks, 256>>>(item_emb);
    i_dir_kernel<<<idir_blocks, 256>>>(user_emb);
    ln_kernel<true><<<ln_blocks, 256>>>(user_emb, item_emb, gamma, beta, u_buf, i_buf);

    // ---- layer 2 ----
    u_dir_kernel<<<udir_blocks, 256>>>(i_buf);
    i_dir_kernel<<<idir_blocks, 256>>>(u_buf);
    ln_kernel<false><<<ln_blocks, 256>>>(u_buf, i_buf, gamma, beta, u_out, i_out);
}

// round 3
// speedup vs baseline: 3.3832x; 2.4208x over previous
#include <cuda_runtime.h>

#define NUSERS 100000
#define NITEMS 200000
#define DIM    128
#define NEDGES 2000000
#define LN_EPS 1e-5f

#define NBUCKETS (NUSERS + NITEMS)          // r-buckets then c-buckets
#define SCAN_BLK 1024
#define NSCANBLK ((NBUCKETS + SCAN_BLK - 1) / SCAN_BLK)   // 293

// ---------------- scratch (device globals; no allocations allowed) ----------
__device__ __align__(16) float g_u_buf [NUSERS * DIM];   // layer-1 user output
__device__ __align__(16) float g_i_buf [NITEMS * DIM];   // layer-1 item output

// edge lists sorted by bucket key: payload = (other index, value-bits)
__device__ __align__(16) int2 g_by_r[NEDGES];            // key r, payload (c, v)
__device__ __align__(16) int2 g_by_c[NEDGES];            // key c, payload (r, v)

__device__ int g_cnt[NBUCKETS];        // histogram
__device__ int g_off[NBUCKETS + 1];    // exclusive-scan offsets (CSR), pristine
__device__ int g_cur[NBUCKETS];        // working cursors for the build scatter
__device__ int g_bsum[NSCANBLK];       // per-block sums for the scan spine

// ---------------- zero counters -----------------------------------------------
__global__ void zero_cnt_kernel() {
    int idx = blockIdx.x * blockDim.x + threadIdx.x;
    if (idx < NBUCKETS) g_cnt[idx] = 0;
}

// ---------------- histogram ---------------------------------------------------
__global__ void hist_kernel(const int* __restrict__ rows, const int* __restrict__ cols) {
    int e = blockIdx.x * blockDim.x + threadIdx.x;
    if (e >= NEDGES) return;
    atomicAdd(&g_cnt[rows[e]], 1);
    atomicAdd(&g_cnt[NUSERS + cols[e]], 1);
}

// ---------------- scan: per-block sums ----------------------------------------
__global__ void scan_bsum_kernel() {
    __shared__ int s[SCAN_BLK];
    int idx = blockIdx.x * SCAN_BLK + threadIdx.x;
    int v = (idx < NBUCKETS) ? g_cnt[idx] : 0;
    s[threadIdx.x] = v;
    __syncthreads();
    for (int o = SCAN_BLK / 2; o > 0; o >>= 1) {
        if (threadIdx.x < o) s[threadIdx.x] += s[threadIdx.x + o];
        __syncthreads();
    }
    if (threadIdx.x == 0) g_bsum[blockIdx.x] = s[0];
}

// ---------------- scan: spine (one block, parallel) ---------------------------
__global__ void scan_spine_kernel() {
    __shared__ int s[SCAN_BLK];
    int t = threadIdx.x;
    int v = (t < NSCANBLK) ? g_bsum[t] : 0;
    s[t] = v;
    __syncthreads();
    for (int o = 1; o < SCAN_BLK; o <<= 1) {
        int x = (t >= o) ? s[t - o] : 0;
        __syncthreads();
        s[t] += x;
        __syncthreads();
    }
    if (t < NSCANBLK) g_bsum[t] = s[t] - v;   // exclusive
    if (t == 0) g_off[NBUCKETS] = 2 * NEDGES;
}

// ---------------- scan: apply block-local exclusive scan ----------------------
__global__ void scan_apply_kernel() {
    __shared__ int s[SCAN_BLK];
    int idx = blockIdx.x * SCAN_BLK + threadIdx.x;
    int v = (idx < NBUCKETS) ? g_cnt[idx] : 0;
    s[threadIdx.x] = v;
    __syncthreads();
    for (int o = 1; o < SCAN_BLK; o <<= 1) {
        int t = (threadIdx.x >= o) ? s[threadIdx.x - o] : 0;
        __syncthreads();
        s[threadIdx.x] += t;
        __syncthreads();
    }
    int excl = s[threadIdx.x] - v + g_bsum[blockIdx.x];
    if (idx < NBUCKETS) {
        g_off[idx] = excl;
        g_cur[idx] = excl;
    }
}

// ---------------- build sorted edge lists -------------------------------------
__global__ void build_kernel(const int* __restrict__ rows,
                             const int* __restrict__ cols,
                             const float* __restrict__ vals) {
    int e = blockIdx.x * blockDim.x + threadIdx.x;
    if (e >= NEDGES) return;
    int r = rows[e];
    int c = cols[e];
    int vb = __float_as_int(vals[e]);
    int p1 = atomicAdd(&g_cur[r], 1);                       // in [0, NEDGES)
    g_by_r[p1] = make_int2(c, vb);
    int p2 = atomicAdd(&g_cur[NUSERS + c], 1) - NEDGES;     // in [0, NEDGES)
    g_by_c[p2] = make_int2(r, vb);
}

// ---------------- fused gather + residual + LayerNorm -------------------------
// warp per destination row: acc = self_emb[row]; acc += v * other_emb[idx]
// over the CSR bucket; then LN in-register; write out. No temps, no atomics.
__global__ void __launch_bounds__(256) gather_ln_kernel(
        const float* __restrict__ self_emb,
        const float* __restrict__ other_emb,
        const int2*  __restrict__ edges,
        const int*   __restrict__ off,      // length n_rows+1, biased by `bias`
        int bias,
        int n_rows,
        const float* __restrict__ gamma,
        const float* __restrict__ beta,
        float* __restrict__ out) {
    int row  = (blockIdx.x * blockDim.x + threadIdx.x) >> 5;
    int lane = threadIdx.x & 31;
    if (row >= n_rows) return;

    int beg = off[row]     - bias;
    int end = off[row + 1] - bias;

    const float4* self4  = reinterpret_cast<const float4*>(self_emb);
    const float4* other4 = reinterpret_cast<const float4*>(other_emb);

    float4 acc = __ldg(&self4[row * 32 + lane]);   // residual

    int p = beg;
    // 2-way unroll for MLP on the dependent edge-list -> gather chain
    for (; p + 1 < end; p += 2) {
        int2 e0 = __ldg(&edges[p]);
        int2 e1 = __ldg(&edges[p + 1]);
        float4 g0 = __ldg(&other4[e0.x * 32 + lane]);
        float4 g1 = __ldg(&other4[e1.x * 32 + lane]);
        float v0 = __int_as_float(e0.y);
        float v1 = __int_as_float(e1.y);
        acc.x += v0 * g0.x + v1 * g1.x;
        acc.y += v0 * g0.y + v1 * g1.y;
        acc.z += v0 * g0.z + v1 * g1.z;
        acc.w += v0 * g0.w + v1 * g1.w;
    }
    if (p < end) {
        int2 e0 = __ldg(&edges[p]);
        float4 g0 = __ldg(&other4[e0.x * 32 + lane]);
        float v0 = __int_as_float(e0.y);
        acc.x += v0 * g0.x;
        acc.y += v0 * g0.y;
        acc.z += v0 * g0.z;
        acc.w += v0 * g0.w;
    }

    // LayerNorm over the 128 values held across the warp
    float s  = acc.x + acc.y + acc.z + acc.w;
    float sq = acc.x * acc.x + acc.y * acc.y + acc.z * acc.z + acc.w * acc.w;
#pragma unroll
    for (int o = 16; o > 0; o >>= 1) {
        s  += __shfl_xor_sync(0xffffffffu, s,  o);
        sq += __shfl_xor_sync(0xffffffffu, sq, o);
    }
    float m    = s * (1.f / DIM);
    float var  = sq * (1.f / DIM) - m * m;
    float rstd = rsqrtf(var + LN_EPS);

    float4 g = __ldg(&reinterpret_cast<const float4*>(gamma)[lane]);
    float4 b = __ldg(&reinterpret_cast<const float4*>(beta )[lane]);

    float4 o;
    o.x = g.x * (acc.x - m) * rstd + b.x;
    o.y = g.y * (acc.y - m) * rstd + b.y;
    o.z = g.z * (acc.z - m) * rstd + b.z;
    o.w = g.w * (acc.w - m) * rstd + b.w;
    reinterpret_cast<float4*>(out)[row * 32 + lane] = o;
}

// ---------------- launch -----------------------------------------------------
extern "C" void kernel_launch(void* const* d_in, const int* in_sizes, int n_in,
                              void* d_out, int out_size) {
    const float* user_emb = (const float*)d_in[0];
    const float* item_emb = (const float*)d_in[1];
    const float* vals     = (const float*)d_in[2];
    const float* gamma    = (const float*)d_in[3];
    const float* beta     = (const float*)d_in[4];
    const int*   rows     = (const int*)d_in[5];
    const int*   cols     = (const int*)d_in[6];

    float* out   = (float*)d_out;
    float* u_out = out;
    float* i_out = out + (size_t)NUSERS * DIM;

    void* p; 
    cudaGetSymbolAddress(&p, g_u_buf);  float* u_buf = (float*)p;
    cudaGetSymbolAddress(&p, g_i_buf);  float* i_buf = (float*)p;
    cudaGetSymbolAddress(&p, g_by_r);   const int2* by_r = (const int2*)p;
    cudaGetSymbolAddress(&p, g_by_c);   const int2* by_c = (const int2*)p;
    cudaGetSymbolAddress(&p, g_off);    const int*  offp = (const int*)p;

    const int cnt_blocks  = (NBUCKETS + 1023) / 1024;              // 293
    const int edge_blocks = (NEDGES + 255) / 256;                  // 7813
    const int u_blocks    = (NUSERS * 32 + 255) / 256;             // 12500
    const int i_blocks    = (NITEMS * 32 + 255) / 256;             // 25000

    // ---- preprocessing: counting sort of edges by both keys ----
    zero_cnt_kernel<<<cnt_blocks, 1024>>>();
    hist_kernel<<<edge_blocks, 256>>>(rows, cols);
    scan_bsum_kernel<<<NSCANBLK, SCAN_BLK>>>();
    scan_spine_kernel<<<1, SCAN_BLK>>>();
    scan_apply_kernel<<<NSCANBLK, SCAN_BLK>>>();
    build_kernel<<<edge_blocks, 256>>>(rows, cols, vals);

    // ---- layer 1 (both directions read the ORIGINAL embeddings) ----
    // users: gather item rows via r-sorted list (off = g_off[0..NUSERS], bias 0)
    gather_ln_kernel<<<u_blocks, 256>>>(user_emb, item_emb, by_r,
                                        offp, 0, NUSERS, gamma, beta, u_buf);
    // items: gather user rows via c-sorted list (off = g_off+NUSERS, bias NEDGES)
    gather_ln_kernel<<<i_blocks, 256>>>(item_emb, user_emb, by_c,
                                        offp + NUSERS, NEDGES, NITEMS, gamma, beta, i_buf);

    // ---- layer 2 ----
    gather_ln_kernel<<<u_blocks, 256>>>(u_buf, i_buf, by_r,
                                        offp, 0, NUSERS, gamma, beta, u_out);
    gather_ln_kernel<<<i_blocks, 256>>>(i_buf, u_buf, by_c,
                                        offp + NUSERS, NEDGES, NITEMS, gamma, beta, i_out);
}